// round 7
// baseline (speedup 1.0000x reference)
#include <cuda_runtime.h>

// Gammatone filterbank: 4 cascaded complex one-pole IIRs.
// B=8, T=32000, C=128. Output [B, T, C] fp32.
//
// Round 6: two independent time chunks per thread (2x ILP on the dependent
// fma2 chain) + packed f32x2 math + per-warp adaptive halo.

#define TT 32000
#define CC 128
#define BB 8
#define LL 320
#define NPAIR (TT / (2 * LL))   // 50 chunk pairs
#define HMAXC 768
#define NTHR 64                 // thread j -> channels 2j, 2j+1

typedef unsigned long long u64;

__device__ __forceinline__ u64 pack2(float lo, float hi) {
    u64 r; asm("mov.b64 %0, {%1, %2};" : "=l"(r) : "f"(lo), "f"(hi)); return r;
}
__device__ __forceinline__ u64 fma2(u64 a, u64 b, u64 c) {
    u64 d; asm("fma.rn.f32x2 %0, %1, %2, %3;" : "=l"(d) : "l"(a), "l"(b), "l"(c)); return d;
}
__device__ __forceinline__ u64 mul2(u64 a, u64 b) {
    u64 d; asm("mul.rn.f32x2 %0, %1, %2;" : "=l"(d) : "l"(a), "l"(b)); return d;
}

// 4-stage cascade, one time step, packed channel pair.
#define CASCADE(s1r,s1i,s2r,s2i,s3r,s3i,s4r,s4i, x) do {   \
    u64 _n;                                                \
    _n  = fma2(cr2, s1r, (x));                             \
    s1i = fma2(cr2, s1i, 0ULL);                            \
    _n  = fma2(cin2, s1i_o, _n);                           \
    s1i = fma2(ci2, s1r_o, s1i);                           \
    s1r = _n;                                              \
    _n  = fma2(cr2, s2r, s1r_o2);                          \
    s2i = fma2(cr2, s2i, s1i_o2);                          \
    (void)0; } while (0)
// (macro above unused; real one below — kept simple and fully explicit)

#undef CASCADE
#define STAGE(sr, si, xr, xi) do {              \
    u64 _nr = fma2(cr2, sr, xr);                \
    _nr = fma2(cin2, si, _nr);                  \
    u64 _ni = fma2(cr2, si, xi);                \
    _ni = fma2(ci2, sr, _ni);                   \
    sr = _nr; si = _ni; } while (0)

#define CASC(P, x) do {                         \
    STAGE(s1r##P, s1i##P, (x), 0ULL);           \
    STAGE(s2r##P, s2i##P, s1r##P, s1i##P);      \
    STAGE(s3r##P, s3i##P, s2r##P, s2i##P);      \
    STAGE(s4r##P, s4i##P, s3r##P, s3i##P); } while (0)

__global__ __launch_bounds__(NTHR)
void gammatone_kernel(const float* __restrict__ inp,
                      const float* __restrict__ coef_re,
                      const float* __restrict__ coef_im,
                      const float* __restrict__ factor,
                      float* __restrict__ out)
{
    __shared__ float2 xs[HMAXC + 2 * LL];

    const int pair = blockIdx.x;      // 0..NPAIR-1
    const int b    = blockIdx.y;      // 0..BB-1
    const int j    = threadIdx.x;     // 0..63 -> channels 2j, 2j+1

    const int t0a = pair * (2 * LL);  // chunk A start
    const int W   = min(t0a, HMAXC);  // staged halo before t0a
    const int total = W + 2 * LL;

    // Stage input window as duplicated float2 (one LDS.64 -> (x,x)).
    const float* ib = inp + b * TT + (t0a - W);
    for (int i = j; i < total; i += NTHR) {
        float v = ib[i];
        xs[i] = make_float2(v, v);
    }
    __syncthreads();

    const float2 crv = ((const float2*)coef_re)[j];
    const float2 civ = ((const float2*)coef_im)[j];
    const float2 fv  = ((const float2*)factor)[j];
    const u64 cr2  = pack2(crv.x,  crv.y);
    const u64 ci2  = pack2(civ.x,  civ.y);
    const u64 cin2 = pack2(-civ.x, -civ.y);
    const u64 f2   = pack2(fv.x,   fv.y);

    // Per-warp adaptive warm-up length.
    float r0 = sqrtf(crv.x * crv.x + civ.x * civ.x);
    float r1 = sqrtf(crv.y * crv.y + civ.y * civ.y);
    float rmax = fminf(fmaxf(r0, r1), 0.9999f);
    int H = (int)ceilf(11.5f / (-__logf(rmax))) + 64;
    H = min(H, HMAXC);
    H = (int)__reduce_max_sync(0xffffffffu, (unsigned)H);

    const int nwA = min(H, W);        // chunk A warm-up (exact when W == t0a)
    const int nwB = min(H, W + LL);   // chunk B warm-up
    const int d   = nwB - nwA;        // B-only prologue length

    u64 s1rA=0,s1iA=0,s2rA=0,s2iA=0,s3rA=0,s3iA=0,s4rA=0,s4iA=0;
    u64 s1rB=0,s1iB=0,s2rB=0,s2iB=0,s3rB=0,s3iB=0,s4rB=0,s4iB=0;

    const u64* base = (const u64*)xs;
    const u64* pA = base + (W - nwA);
    const u64* pB = base + (W + LL - nwB);

    // Phase 1: B-only warm-up (only for the first two chunk pairs).
    #pragma unroll 4
    for (int i = 0; i < d; ++i)
        CASC(B, pB[i]);

    // Phase 2: both chains warm in lockstep (2x independent fma2 chains).
    pB += d;
    #pragma unroll 2
    for (int i = 0; i < nwA; ++i) {
        CASC(A, pA[i]);
        CASC(B, pB[i]);
    }

    // Phase 3: both chains emit.
    const u64* eA = base + W;
    const u64* eB = eA + LL;
    u64* oA = (u64*)(out + ((size_t)(b * TT + t0a)) * CC) + j;
    u64* oB = oA + (size_t)LL * (CC / 2);
    #pragma unroll 2
    for (int i = 0; i < LL; ++i) {
        CASC(A, eA[i]);
        oA[(size_t)i * (CC / 2)] = mul2(s4rA, f2);
        CASC(B, eB[i]);
        oB[(size_t)i * (CC / 2)] = mul2(s4rB, f2);
    }
}

extern "C" void kernel_launch(void* const* d_in, const int* in_sizes, int n_in,
                              void* d_out, int out_size)
{
    const float* inp     = (const float*)d_in[0];
    const float* coef_re = (const float*)d_in[1];
    const float* coef_im = (const float*)d_in[2];
    const float* factor  = (const float*)d_in[3];
    float* out = (float*)d_out;

    dim3 grid(NPAIR, BB);
    gammatone_kernel<<<grid, NTHR>>>(inp, coef_re, coef_im, factor, out);
}

// round 8
// speedup vs baseline: 1.6162x; 1.6162x over previous
#include <cuda_runtime.h>

// Gammatone filterbank: 4 cascaded complex one-pole IIRs.
// B=8, T=32000, C=128. Output [B, T, C] fp32.
//
// Round 8: 128-thread blocks (cover all 4 SMSPs; SMSP = wid%4, so 64-thread
// blocks left half the SM idle). One channel per thread; the two f32x2 lanes
// carry two consecutive time chunks. Per-warp (32-channel) adaptive halo,
// warp->channel-group rotation to balance heavy halos across SMSPs.

#define TT 32000
#define CC 128
#define BB 8
#define LLC 433
#define PAIRS 37            // 37 pairs * 2 * 433 = 32042 >= 32000 (tail guarded)
#define WH 768              // staged halo length for pair > 0 (866 > 768 always)
#define NTHR 128

typedef unsigned long long u64;

__device__ __forceinline__ u64 pack2(float lo, float hi) {
    u64 r; asm("mov.b64 %0, {%1, %2};" : "=l"(r) : "f"(lo), "f"(hi)); return r;
}
__device__ __forceinline__ void unpack2(float& lo, float& hi, u64 v) {
    asm("mov.b64 {%0, %1}, %2;" : "=f"(lo), "=f"(hi) : "l"(v));
}
__device__ __forceinline__ u64 fma2(u64 a, u64 b, u64 c) {
    u64 d; asm("fma.rn.f32x2 %0, %1, %2, %3;" : "=l"(d) : "l"(a), "l"(b), "l"(c)); return d;
}
__device__ __forceinline__ u64 mul2(u64 a, u64 b) {
    u64 d; asm("mul.rn.f32x2 %0, %1, %2;" : "=l"(d) : "l"(a), "l"(b)); return d;
}

// One complex one-pole stage, both f32x2 lanes (= two time chunks).
#define STAGE(sr, si, xr, xi) do {              \
    u64 _nr = fma2(cr2, sr, xr);                \
    _nr = fma2(cin2, si, _nr);                  \
    u64 _ni = fma2(cr2, si, xi);                \
    _ni = fma2(ci2, sr, _ni);                   \
    sr = _nr; si = _ni; } while (0)

#define CASC(x) do {                            \
    STAGE(s1r, s1i, (x), 0ULL);                 \
    STAGE(s2r, s2i, s1r, s1i);                  \
    STAGE(s3r, s3i, s2r, s2i);                  \
    STAGE(s4r, s4i, s3r, s3i); } while (0)

__global__ __launch_bounds__(NTHR)
void gammatone_kernel(const float* __restrict__ inp,
                      const float* __restrict__ coef_re,
                      const float* __restrict__ coef_im,
                      const float* __restrict__ factor,
                      float* __restrict__ out)
{
    __shared__ float2 xs[WH + LLC];   // 1201 entries (9.6 KB); pair0 uses 866

    const int pair = blockIdx.x;      // 0..PAIRS-1
    const int b    = blockIdx.y;      // 0..BB-1
    const int tid  = threadIdx.x;
    const int w    = tid >> 5;
    const int lane = tid & 31;

    // Rotate channel-group roles across SMSPs (bids on one SM differ by ~148
    // which is 0 mod 4; the >>2 term breaks the collision).
    const unsigned bid = blockIdx.x + gridDim.x * blockIdx.y;
    const int role = (w + bid + (bid >> 2)) & 3;
    const int c = role * 32 + lane;   // this thread's channel

    const int tA = pair * (2 * LLC);  // chunk A start; chunk B = tA + LLC
    const bool p0 = (pair == 0);
    const float* ib = inp + b * TT;

    // Stage input window.
    if (p0) {
        // Exact run from t=0 over both chunks: lanes see identical stream.
        for (int i = tid; i < 2 * LLC; i += NTHR) {
            float v = ib[i];
            xs[i] = make_float2(v, v);
        }
    } else {
        // Entry i: lane0 = x[tA - WH + i], lane1 = x[tA - WH + i + LLC].
        const int base = tA - WH;
        for (int i = tid; i < WH + LLC; i += NTHR) {
            float v0 = ib[base + i];
            int j1 = base + i + LLC;
            if (j1 > TT - 1) j1 = TT - 1;  // tail clamp (garbage never stored)
            xs[i] = make_float2(v0, ib[j1]);
        }
    }
    __syncthreads();

    const float cr = coef_re[c];
    const float ci = coef_im[c];
    const float f  = factor[c];
    const u64 cr2  = pack2(cr,  cr);
    const u64 ci2  = pack2(ci,  ci);
    const u64 cin2 = pack2(-ci, -ci);
    const u64 f2   = pack2(f,   f);

    // Per-warp adaptive warm-up length (32-channel granularity).
    float r = fminf(sqrtf(cr * cr + ci * ci), 0.9999f);
    int H = (int)ceilf(11.5f / (-__logf(r))) + 64;
    H = min(H, WH);
    H = (int)__reduce_max_sync(0xffffffffu, (unsigned)H);

    u64 s1r = 0, s1i = 0, s2r = 0, s2i = 0;
    u64 s3r = 0, s3i = 0, s4r = 0, s4i = 0;

    const u64* xb = (const u64*)xs;

    if (p0) {
        // Both lanes compute the exact stream; single store per step.
        float* ob = out + ((size_t)b * TT) * CC + c;
        #pragma unroll 4
        for (int i = 0; i < 2 * LLC; ++i) {
            CASC(xb[i]);
            float lo, hi;
            unpack2(lo, hi, mul2(s4r, f2));
            ob[(size_t)i * CC] = lo;
        }
    } else {
        // Warm-up: H steps ending at entry WH (both lanes warm simultaneously).
        const u64* xp = xb + (WH - H);
        #pragma unroll 4
        for (int i = 0; i < H; ++i)
            CASC(xp[i]);

        // Emit: lane0 -> rows tA+i, lane1 -> rows tA+LLC+i (guard tail).
        const u64* xe = xb + WH;
        float* oA = out + ((size_t)(b * TT + tA)) * CC + c;
        float* oB = oA + (size_t)LLC * CC;
        const int nB = min(LLC, TT - (tA + LLC));  // lane1 valid rows
        #pragma unroll 4
        for (int i = 0; i < LLC; ++i) {
            CASC(xe[i]);
            float lo, hi;
            unpack2(lo, hi, mul2(s4r, f2));
            oA[(size_t)i * CC] = lo;
            if (i < nB)
                oB[(size_t)i * CC] = hi;
        }
    }
}

extern "C" void kernel_launch(void* const* d_in, const int* in_sizes, int n_in,
                              void* d_out, int out_size)
{
    const float* inp     = (const float*)d_in[0];
    const float* coef_re = (const float*)d_in[1];
    const float* coef_im = (const float*)d_in[2];
    const float* factor  = (const float*)d_in[3];
    float* out = (float*)d_out;

    dim3 grid(PAIRS, BB);
    gammatone_kernel<<<grid, NTHR>>>(inp, coef_re, coef_im, factor, out);
}

// round 9
// speedup vs baseline: 1.8668x; 1.1551x over previous
#include <cuda_runtime.h>

// Gammatone filterbank: 4 cascaded complex one-pole IIRs.
// B=8, T=32000, C=128. Output [B, T, C] fp32.
//
// Round 9: DELAYED-UPDATE cascade. Each stage updates from the previous
// step's value of the stage above: s_k[t] = c*s_k[t-1] + s_{k-1}[t-1].
// This equals the true cascade output delayed by 3 samples (exact), but the
// 4 complex stage updates per step become INDEPENDENT -> per-step critical
// path drops from ~8 dependent fma2 to 2, unblocking the per-warp ~110cyc/step
// serialization seen in R5-R8. Store index shifted by 3; 3 extra steps/chunk.

#define TT 32000
#define CC 128
#define BB 8
#define LLC 433
#define PAIRS 37            // 37 * 2 * 433 = 32042 >= 32000 (tail guarded)
#define WH 768
#define NTHR 128

typedef unsigned long long u64;

__device__ __forceinline__ u64 pack2(float lo, float hi) {
    u64 r; asm("mov.b64 %0, {%1, %2};" : "=l"(r) : "f"(lo), "f"(hi)); return r;
}
__device__ __forceinline__ void unpack2(float& lo, float& hi, u64 v) {
    asm("mov.b64 {%0, %1}, %2;" : "=f"(lo), "=f"(hi) : "l"(v));
}
__device__ __forceinline__ u64 fma2(u64 a, u64 b, u64 c) {
    u64 d; asm("fma.rn.f32x2 %0, %1, %2, %3;" : "=l"(d) : "l"(a), "l"(b), "l"(c)); return d;
}
__device__ __forceinline__ u64 mul2(u64 a, u64 b) {
    u64 d; asm("mul.rn.f32x2 %0, %1, %2;" : "=l"(d) : "l"(a), "l"(b)); return d;
}

// Delayed-update step: all stages read previous-step values.
// In-place update order s4,s3,s2,s1 preserves the "old" reads.
// complex: s' = c*s + u  ->  sr' = cr*sr - ci*si + ur ; si' = cr*si + ci*sr + ui
#define DSTEP(x) do {                                       \
    u64 n4r = fma2(cr2, s4r, s3r); n4r = fma2(cin2, s4i, n4r); \
    u64 n4i = fma2(cr2, s4i, s3i); n4i = fma2(ci2,  s4r, n4i); \
    u64 n3r = fma2(cr2, s3r, s2r); n3r = fma2(cin2, s3i, n3r); \
    u64 n3i = fma2(cr2, s3i, s2i); n3i = fma2(ci2,  s3r, n3i); \
    u64 n2r = fma2(cr2, s2r, s1r); n2r = fma2(cin2, s2i, n2r); \
    u64 n2i = fma2(cr2, s2i, s1i); n2i = fma2(ci2,  s2r, n2i); \
    u64 n1r = fma2(cr2, s1r, (x)); n1r = fma2(cin2, s1i, n1r); \
    u64 n1i = mul2(cr2, s1i);      n1i = fma2(ci2,  s1r, n1i); \
    s4r = n4r; s4i = n4i; s3r = n3r; s3i = n3i;             \
    s2r = n2r; s2i = n2i; s1r = n1r; s1i = n1i; } while (0)

__global__ __launch_bounds__(NTHR)
void gammatone_kernel(const float* __restrict__ inp,
                      const float* __restrict__ coef_re,
                      const float* __restrict__ coef_im,
                      const float* __restrict__ factor,
                      float* __restrict__ out)
{
    __shared__ float2 xs[WH + LLC + 4];

    const int pair = blockIdx.x;      // 0..PAIRS-1
    const int b    = blockIdx.y;      // 0..BB-1
    const int tid  = threadIdx.x;
    const int w    = tid >> 5;
    const int lane = tid & 31;

    // Rotate channel-group roles so heavy-halo warps spread across SMSPs.
    const unsigned bid = blockIdx.x + gridDim.x * blockIdx.y;
    const int role = (w + bid + (bid >> 2)) & 3;
    const int c = role * 32 + lane;

    const int tA = pair * (2 * LLC);
    const bool p0 = (pair == 0);
    const float* ib = inp + b * TT;

    if (p0) {
        // Exact run from t=0; both lanes identical. Need x[0 .. 2L+2].
        for (int i = tid; i < 2 * LLC + 3; i += NTHR) {
            float v = ib[i];
            xs[i] = make_float2(v, v);
        }
    } else {
        // Entry i: lane0 = x[tA-WH+i], lane1 = x[tA-WH+i+LLC] (clamped tail:
        // garbage only ever enters s1..s3 after the final stored output).
        const int base = tA - WH;
        for (int i = tid; i < WH + LLC + 3; i += NTHR) {
            float v0 = ib[base + i];
            int j1 = base + i + LLC;
            if (j1 > TT - 1) j1 = TT - 1;
            xs[i] = make_float2(v0, ib[j1]);
        }
    }
    __syncthreads();

    const float cr = coef_re[c];
    const float ci = coef_im[c];
    const float f  = factor[c];
    const u64 cr2  = pack2(cr,  cr);
    const u64 ci2  = pack2(ci,  ci);
    const u64 cin2 = pack2(-ci, -ci);
    const u64 f2   = pack2(f,   f);

    // Per-warp adaptive warm-up length.
    float r = fminf(sqrtf(cr * cr + ci * ci), 0.9999f);
    int H = (int)ceilf(10.5f / (-__logf(r))) + 56;
    H = min(H, WH);
    H = (int)__reduce_max_sync(0xffffffffu, (unsigned)H);

    u64 s1r = 0, s1i = 0, s2r = 0, s2i = 0;
    u64 s3r = 0, s3i = 0, s4r = 0, s4i = 0;

    const u64* xb = (const u64*)xs;

    if (p0) {
        // 3-step priming (no store), then 2L stores of the 3-delayed s4.
        DSTEP(xb[0]); DSTEP(xb[1]); DSTEP(xb[2]);
        float* ob = out + ((size_t)b * TT) * CC + c;
        #pragma unroll 4
        for (int i = 0; i < 2 * LLC; ++i) {
            DSTEP(xb[i + 3]);
            float lo, hi;
            unpack2(lo, hi, mul2(s4r, f2));
            ob[(size_t)i * CC] = lo;
        }
    } else {
        // Warm-up: H+3 steps ending at entry WH+2.
        const u64* xp = xb + (WH - H);
        const int nwu = H + 3;
        #pragma unroll 4
        for (int i = 0; i < nwu; ++i)
            DSTEP(xp[i]);

        // Emit: process entry WH+3+i, store out row tA+i (lane0) / tA+L+i (lane1).
        const u64* xe = xb + (WH + 3);
        float* oA = out + ((size_t)(b * TT + tA)) * CC + c;
        float* oB = oA + (size_t)LLC * CC;
        const int nB = min(LLC, TT - (tA + LLC));
        #pragma unroll 4
        for (int i = 0; i < LLC; ++i) {
            DSTEP(xe[i]);
            float lo, hi;
            unpack2(lo, hi, mul2(s4r, f2));
            oA[(size_t)i * CC] = lo;
            if (i < nB)
                oB[(size_t)i * CC] = hi;
        }
    }
}

extern "C" void kernel_launch(void* const* d_in, const int* in_sizes, int n_in,
                              void* d_out, int out_size)
{
    const float* inp     = (const float*)d_in[0];
    const float* coef_re = (const float*)d_in[1];
    const float* coef_im = (const float*)d_in[2];
    const float* factor  = (const float*)d_in[3];
    float* out = (float*)d_out;

    dim3 grid(PAIRS, BB);
    gammatone_kernel<<<grid, NTHR>>>(inp, coef_re, coef_im, factor, out);
}

// round 10
// speedup vs baseline: 2.5051x; 1.3419x over previous
#include <cuda_runtime.h>

// Gammatone filterbank: 4 cascaded complex one-pole IIRs.
// B=8, T=32000, C=128. Output [B, T, C] fp32.
//
// Round 10: FFMA2 is half-rate (rt=4/SMSP) -> one warp saturates an SMSP's
// fp32 pipe. Launch exactly 592 warps (148 blocks x 4), give each warp ONE
// long chunk-pair (both f32x2 lanes = two time chunks of one channel),
// with per-channel-group chunk lengths balanced against their warm-up halo:
//   group g (channels 32g..32g+31): N_g pairs of length L_g, H_g + L_g ~ const.
// Halo work drops from 45% to ~29% of total. Zero-padded staging makes the
// t<0 boundary exact (zero initial state), single uniform code path.

#define TT 32000
#define CC 128
#define BB 8
#define NTHR 128
#define NBLK 148
#define WPB  74            // warps per batch
#define WBUF 1280          // per-warp staging entries (float2)

typedef unsigned long long u64;

__device__ __forceinline__ u64 pack2(float lo, float hi) {
    u64 r; asm("mov.b64 %0, {%1, %2};" : "=l"(r) : "f"(lo), "f"(hi)); return r;
}
__device__ __forceinline__ void unpack2(float& lo, float& hi, u64 v) {
    asm("mov.b64 {%0, %1}, %2;" : "=f"(lo), "=f"(hi) : "l"(v));
}
__device__ __forceinline__ u64 fma2(u64 a, u64 b, u64 c) {
    u64 d; asm("fma.rn.f32x2 %0, %1, %2, %3;" : "=l"(d) : "l"(a), "l"(b), "l"(c)); return d;
}
__device__ __forceinline__ u64 mul2(u64 a, u64 b) {
    u64 d; asm("mul.rn.f32x2 %0, %1, %2;" : "=l"(d) : "l"(a), "l"(b)); return d;
}

// Delayed-update step (all 4 stages read previous-step values -> 4 independent
// 2-deep FMA chains; equals true cascade delayed by 3 samples, exact).
#define DSTEP(x) do {                                          \
    u64 n4r = fma2(cr2, s4r, s3r); n4r = fma2(cin2, s4i, n4r); \
    u64 n4i = fma2(cr2, s4i, s3i); n4i = fma2(ci2,  s4r, n4i); \
    u64 n3r = fma2(cr2, s3r, s2r); n3r = fma2(cin2, s3i, n3r); \
    u64 n3i = fma2(cr2, s3i, s2i); n3i = fma2(ci2,  s3r, n3i); \
    u64 n2r = fma2(cr2, s2r, s1r); n2r = fma2(cin2, s2i, n2r); \
    u64 n2i = fma2(cr2, s2i, s1i); n2i = fma2(ci2,  s2r, n2i); \
    u64 n1r = fma2(cr2, s1r, (x)); n1r = fma2(cin2, s1i, n1r); \
    u64 n1i = mul2(cr2, s1i);      n1i = fma2(ci2,  s1r, n1i); \
    s4r = n4r; s4i = n4i; s3r = n3r; s3i = n3i;                \
    s2r = n2r; s2i = n2i; s1r = n1r; s1i = n1i; } while (0)

__global__ __launch_bounds__(NTHR)
void gammatone_kernel(const float* __restrict__ inp,
                      const float* __restrict__ coef_re,
                      const float* __restrict__ coef_im,
                      const float* __restrict__ factor,
                      float* __restrict__ out)
{
    __shared__ float2 xs[4][WBUF];   // one private window per warp (40 KB)

    const int tid  = threadIdx.x;
    const int widx = tid >> 5;
    const int lane = tid & 31;

    const int w = blockIdx.x * 4 + widx;   // 0..591
    const int b = w / WPB;                 // batch
    const int r = w % WPB;

    // Per-group chunk schedule: N = {27,18,15,14} pairs, L balanced vs halo.
    int g, k, L;
    if      (r < 27) { g = 0; k = r;      L = 593;  }
    else if (r < 45) { g = 1; k = r - 27; L = 889;  }
    else if (r < 60) { g = 2; k = r - 45; L = 1067; }
    else             { g = 3; k = r - 60; L = 1143; }
    const int hcap = WBUF - L - 4;
    const int c  = g * 32 + lane;          // channel
    const int tA = k * 2 * L;              // lane0 chunk start; lane1 = tA + L

    const float cr = coef_re[c];
    const float ci = coef_im[c];
    const float f  = factor[c];
    const u64 cr2  = pack2(cr,  cr);
    const u64 ci2  = pack2(ci,  ci);
    const u64 cin2 = pack2(-ci, -ci);
    const u64 f2   = pack2(f,   f);

    // Per-warp adaptive warm-up length (warp = one 32-channel group).
    float rr = fminf(sqrtf(cr * cr + ci * ci), 0.9999f);
    int H = (int)ceilf(10.0f / (-__logf(rr))) + 48;
    H = min(H, hcap);
    H = (int)__reduce_max_sync(0xffffffffu, (unsigned)H);

    // Stage zero-padded input window (zero-pad = exact zero initial state).
    // Entry i: lane0 = x[tA-H+i], lane1 = x[tA+L-H+i].
    const float* ib = inp + b * TT;
    const int total = H + L + 3;
    const int base0 = tA - H;
    const int base1 = tA + L - H;
    float2* xw = xs[widx];
    for (int i = lane; i < total; i += 32) {
        int j0 = base0 + i;
        int j1 = base1 + i;
        float v0 = (j0 >= 0 && j0 < TT) ? ib[j0] : 0.0f;
        float v1 = (j1 >= 0 && j1 < TT) ? ib[j1] : 0.0f;
        xw[i] = make_float2(v0, v1);
    }
    __syncwarp();

    u64 s1r = 0, s1i = 0, s2r = 0, s2i = 0;
    u64 s3r = 0, s3i = 0, s4r = 0, s4i = 0;

    const u64* xb = (const u64*)xw;

    // Warm-up: H + 3 steps (3 extra prime the delayed pipeline).
    const int nwu = H + 3;
    #pragma unroll 4
    for (int i = 0; i < nwu; ++i)
        DSTEP(xb[i]);

    // Emit: step i consumes entry H+3+i; s4 = y[tA+i] (lane0) / y[tA+L+i] (lane1).
    const u64* xe = xb + nwu;
    float* oA = out + ((size_t)(b * TT + tA)) * CC + c;
    float* oB = oA + (size_t)L * CC;
    const int nB = min(L, TT - (tA + L));   // lane1 valid rows (tail clamp)
    #pragma unroll 4
    for (int i = 0; i < L; ++i) {
        DSTEP(xe[i]);
        float lo, hi;
        unpack2(lo, hi, mul2(s4r, f2));
        oA[(size_t)i * CC] = lo;
        if (i < nB)
            oB[(size_t)i * CC] = hi;
    }
}

extern "C" void kernel_launch(void* const* d_in, const int* in_sizes, int n_in,
                              void* d_out, int out_size)
{
    const float* inp     = (const float*)d_in[0];
    const float* coef_re = (const float*)d_in[1];
    const float* coef_im = (const float*)d_in[2];
    const float* factor  = (const float*)d_in[3];
    float* out = (float*)d_out;

    gammatone_kernel<<<NBLK, NTHR>>>(inp, coef_re, coef_im, factor, out);
}